// round 11
// baseline (speedup 1.0000x reference)
#include <cuda_runtime.h>
#include <math.h>

#define BATCH 64
#define NG    32
#define CIN   128
#define COUT  128
#define LMAX  16
#define NR    (BATCH*LMAX*2)   // 2048 rows (b,m,ri)

// ---------------- scratch (device globals; no allocation allowed) ----------
__device__ float g_F[(size_t)BATCH*LMAX*2*NG*CIN];     // [b][m][ri][j][i]
// coef/chat layout: [l][m][ri][b][c]  -> valid region per l = first (l+1)*128 rows
__device__ float g_coef[(size_t)LMAX*2048*CIN];
__device__ float g_chat[(size_t)LMAX*2048*COUT];
__device__ float g_G[(size_t)BATCH*NG*LMAX*2*COUT];    // [b][j][m][ri][o]
__device__ float g_Qw[LMAX*LMAX*NG];                   // [l][m][j] * wj * s_l
__device__ float g_Qs[LMAX*LMAX*NG];                   // [l][m][j] * k_m
__device__ float g_cosT[LMAX*NG];                      // [m][p]
__device__ float g_sinT[LMAX*NG];

// ---------------- init: Legendre + trig tables, fp32, 512-way parallel -----
__global__ void init_tables() {
    int t = threadIdx.x;                  // 0..511
    int m = t >> 5, j = t & 31;           // one thread per (m, j)
    float sx, cx;
    sincospif((j + 0.5f) / NG, &sx, &cx);
    float wj = sx * ((float)M_PI / NG) * (2.0f * (float)M_PI / NG);

    for (int l = 0; l < m; l++) {
        g_Qw[(l*LMAX + m)*NG + j] = 0.f;
        g_Qs[(l*LMAX + m)*NG + j] = 0.f;
    }

    float Pmm = 1.0f, invf = 1.0f;
    for (int mm = 1; mm <= m; mm++) Pmm = -(2.0f*mm - 1.0f) * sx * Pmm;
    for (int tt = 1; tt <= 2*m; tt++) invf /= (float)tt;
    float rat = invf;
    float pl_2 = 0.0f, pl_1 = 0.0f, pl = 0.0f;
    const float inv4pi = 1.0f / (4.0f * (float)M_PI);
    for (int l = m; l < LMAX; l++) {
        if (l == m)        pl = Pmm;
        else if (l == m+1) pl = (2.0f*m + 1.0f) * cx * Pmm;
        else               pl = ((2.0f*l - 1.0f)*cx*pl_1 - (l + m - 1.0f)*pl_2) / (float)(l - m);
        float Nlm = sqrtf((2.0f*l + 1.0f) * inv4pi * rat);
        float q   = Nlm * pl;
        float sl  = 2.0f*(float)M_PI * sqrtf(4.0f*(float)M_PI / (2.0f*l + 1.0f));
        float km  = (m == 0) ? 1.0f : 2.0f;
        g_Qw[(l*LMAX + m)*NG + j] = q * wj * sl;
        g_Qs[(l*LMAX + m)*NG + j] = q * km;
        pl_2 = pl_1; pl_1 = pl;
        rat *= (float)(l + 1 - m) / (float)(l + 1 + m);
    }

    float sa, ca;
    sincospif(2.0f * (float)m * (float)j / (float)NG, &sa, &ca);
    g_cosT[m*NG + j] = ca;
    g_sinT[m*NG + j] = sa;
}

// ---------------- A: real DFT over phi (half-split), float2 channels -------
__global__ void __launch_bounds__(64) kA(const float* __restrict__ in) {
    int bj = blockIdx.x;                  // b*32 + j (theta)
    int b = bj >> 5, j = bj & 31;
    int t = threadIdx.x;                  // channel pair 0..63
    __shared__ float2 tcs[16][16];        // (cos, sin) packed
    for (int q = t; q < 256; q += 64) {
        int m = q >> 4, p = q & 15;
        tcs[m][p] = make_float2(g_cosT[m*NG + p], g_sinT[m*NG + p]);
    }
    __syncthreads();

    const float2* src = (const float2*)in + (size_t)bj * NG * 64 + t;
    float2 xe[16], xo[16];
#pragma unroll
    for (int p = 0; p < 16; p++) {
        float2 a = src[p*64], c = src[(p+16)*64];
        xe[p] = make_float2(a.x + c.x, a.y + c.y);
        xo[p] = make_float2(a.x - c.x, a.y - c.y);
    }

    float2* Fout = (float2*)g_F;
#pragma unroll
    for (int m = 0; m < 16; m++) {
        float2 fr = make_float2(0.f, 0.f), fi = make_float2(0.f, 0.f);
#pragma unroll
        for (int p = 0; p < 16; p++) {
            float2 cs = tcs[m][p];
            float2 x = (m & 1) ? xo[p] : xe[p];
            fr.x += x.x*cs.x; fr.y += x.y*cs.x;
            fi.x -= x.x*cs.y; fi.y -= x.y*cs.y;
        }
        size_t base = ((((size_t)b*16 + m)*2 + 0)*NG + j)*64 + t;
        Fout[base]          = fr;
        Fout[base + NG*64]  = fi;   // ri=1
    }
}

// ---------------- B: Legendre analysis with reflection symmetry ------------
// writes coef in [l][m][ri][b] row order; skips l < m (zero rows never read)
__global__ void __launch_bounds__(64) kB() {
    int r = blockIdx.x;                   // (b*16+m)*2+ri
    int b = r >> 5, m = (r >> 1) & 15, ri = r & 1;
    int t = threadIdx.x;
    __shared__ float sq[16][16];          // Qw[l][m][j], j<16
    for (int q = t; q < 256; q += 64) {
        int l = q >> 4, j = q & 15;
        sq[l][j] = g_Qw[(l*LMAX + m)*NG + j];
    }
    __syncthreads();

    const float2* src = (const float2*)g_F + (size_t)r * NG * 64 + t;
    float2 fe[16], fo[16];
#pragma unroll
    for (int j = 0; j < 16; j++) {
        float2 a = src[j*64], c = src[(31-j)*64];
        fe[j] = make_float2(a.x + c.x, a.y + c.y);
        fo[j] = make_float2(a.x - c.x, a.y - c.y);
    }

    float2* Cout = (float2*)g_coef;
    size_t rowbase = (size_t)(m*2 + ri)*64 + b;   // within-l row offset
    if ((m & 1) == 0) {
#pragma unroll
        for (int l = 0; l < 16; l++) {
            if (l < m) continue;
            float2 acc = make_float2(0.f, 0.f);
#pragma unroll
            for (int j = 0; j < 16; j++) {
                float q = sq[l][j];
                float2 f = (l & 1) ? fo[j] : fe[j];
                acc.x += q*f.x; acc.y += q*f.y;
            }
            Cout[((size_t)l*2048 + rowbase)*64 + t] = acc;
        }
    } else {
#pragma unroll
        for (int l = 0; l < 16; l++) {
            if (l < m) continue;
            float2 acc = make_float2(0.f, 0.f);
#pragma unroll
            for (int j = 0; j < 16; j++) {
                float q = sq[l][j];
                float2 f = (l & 1) ? fe[j] : fo[j];
                acc.x += q*f.x; acc.y += q*f.y;
            }
            Cout[((size_t)l*2048 + rowbase)*64 + t] = acc;
        }
    }
}

// ---------------- C: per-degree channel mix, 64-row tiles, double-buffered -
// degree l has (l+1)*128 valid rows = (l+1)*2 tiles of 64; skip mt > 2l+1
__global__ void __launch_bounds__(256) kC(const float* __restrict__ w) {
    int l = blockIdx.y, mt = blockIdx.x;
    if (mt > 2*l + 1) return;             // zero region: skip
    const float* A = g_coef + ((size_t)l*2048 + (size_t)mt*64)*CIN;
    const float* B = w + l*COUT;          // w[i][l][o], k-stride = LMAX*COUT
    float* C = g_chat + ((size_t)l*2048 + (size_t)mt*64)*COUT;

    __shared__ float As[2][16][68];       // [k][row], padded
    __shared__ float Bs[2][16][128];      // [k][col]
    int tid = threadIdx.x;
    int tx = tid & 15, ty = tid >> 4;     // tx: 8-col group, ty: 4-row group
    float acc[4][8] = {};

    // preload buffer 0
#pragma unroll
    for (int e = 0; e < 4; e++) {
        int lin = tid + e*256;
        As[0][lin & 15][lin >> 4] = A[(lin >> 4)*CIN + (lin & 15)];
    }
#pragma unroll
    for (int e = 0; e < 8; e++) {
        int lin = tid + e*256;
        Bs[0][lin >> 7][lin & 127] = B[(size_t)(lin >> 7) * (LMAX*COUT) + (lin & 127)];
    }
    __syncthreads();

    for (int it = 0; it < 8; it++) {
        int cur = it & 1;
        if (it < 7) {
            int k0 = (it + 1) * 16, nxt = cur ^ 1;
#pragma unroll
            for (int e = 0; e < 4; e++) {
                int lin = tid + e*256;
                As[nxt][lin & 15][lin >> 4] = A[(lin >> 4)*CIN + k0 + (lin & 15)];
            }
#pragma unroll
            for (int e = 0; e < 8; e++) {
                int lin = tid + e*256;
                Bs[nxt][lin >> 7][lin & 127] =
                    B[(size_t)(k0 + (lin >> 7)) * (LMAX*COUT) + (lin & 127)];
            }
        }
#pragma unroll
        for (int k = 0; k < 16; k++) {
            float4 a0 = *(const float4*)&As[cur][k][ty*4];
            float4 b0 = *(const float4*)&Bs[cur][k][tx*8];
            float4 b1 = *(const float4*)&Bs[cur][k][tx*8 + 4];
            float av[4] = {a0.x, a0.y, a0.z, a0.w};
            float bv[8] = {b0.x,b0.y,b0.z,b0.w,b1.x,b1.y,b1.z,b1.w};
#pragma unroll
            for (int i2 = 0; i2 < 4; i2++)
#pragma unroll
                for (int j2 = 0; j2 < 8; j2++)
                    acc[i2][j2] += av[i2] * bv[j2];
        }
        __syncthreads();
    }
#pragma unroll
    for (int i2 = 0; i2 < 4; i2++) {
        *(float4*)&C[(ty*4 + i2)*COUT + tx*8]     =
            make_float4(acc[i2][0], acc[i2][1], acc[i2][2], acc[i2][3]);
        *(float4*)&C[(ty*4 + i2)*COUT + tx*8 + 4] =
            make_float4(acc[i2][4], acc[i2][5], acc[i2][6], acc[i2][7]);
    }
}

// ---------------- D: Legendre synthesis with reflection symmetry -----------
__global__ void __launch_bounds__(64) kD() {
    int r = blockIdx.x;                   // (b*16+m)*2+ri
    int ri = r & 1, m = (r >> 1) & 15, b = r >> 5;
    int t = threadIdx.x;
    __shared__ float sq[16][16];          // Qs[l][m][j], j<16 (incl. k_m)
    for (int q = t; q < 256; q += 64) {
        int l = q >> 4, j = q & 15;
        sq[l][j] = g_Qs[(l*LMAX + m)*NG + j];
    }
    __syncthreads();

    float2 ch[16];
    const float2* src = (const float2*)g_chat;
    size_t rowbase = (size_t)(m*2 + ri)*64 + b;
#pragma unroll
    for (int l = 0; l < 16; l++)
        ch[l] = (l >= m) ? src[((size_t)l*2048 + rowbase)*64 + t]
                         : make_float2(0.f, 0.f);

    float2* Gout = (float2*)g_G;
    size_t gbase = ((((size_t)b*NG)*16 + m)*2 + ri)*64 + t;
    const size_t jstride = (size_t)16*2*64;

    if ((m & 1) == 0) {
#pragma unroll
        for (int j = 0; j < 16; j++) {
            float2 Ge = make_float2(0.f,0.f), Go = make_float2(0.f,0.f);
#pragma unroll
            for (int l = 0; l < 16; l++) {
                float q = sq[l][j];
                if (l & 1) { Go.x += q*ch[l].x; Go.y += q*ch[l].y; }
                else       { Ge.x += q*ch[l].x; Ge.y += q*ch[l].y; }
            }
            Gout[gbase + (size_t)j*jstride]      = make_float2(Ge.x+Go.x, Ge.y+Go.y);
            Gout[gbase + (size_t)(31-j)*jstride] = make_float2(Ge.x-Go.x, Ge.y-Go.y);
        }
    } else {
#pragma unroll
        for (int j = 0; j < 16; j++) {
            float2 Ge = make_float2(0.f,0.f), Go = make_float2(0.f,0.f);
#pragma unroll
            for (int l = 0; l < 16; l++) {
                float q = sq[l][j];
                if (l & 1) { Ge.x += q*ch[l].x; Ge.y += q*ch[l].y; }
                else       { Go.x += q*ch[l].x; Go.y += q*ch[l].y; }
            }
            Gout[gbase + (size_t)j*jstride]      = make_float2(Ge.x+Go.x, Ge.y+Go.y);
            Gout[gbase + (size_t)(31-j)*jstride] = make_float2(Ge.x-Go.x, Ge.y-Go.y);
        }
    }
}

// ---------------- E: inverse real DFT over phi (half-split) + bias ---------
__global__ void __launch_bounds__(64) kE(const float* __restrict__ bias,
                                         float* __restrict__ out) {
    int bj = blockIdx.x;                  // b*32 + j (theta)
    int t = threadIdx.x;                  // channel pair
    __shared__ float2 tcs[16][16];        // (cos, sin) packed
    for (int q = t; q < 256; q += 64) {
        int m = q >> 4, p = q & 15;
        tcs[m][p] = make_float2(g_cosT[m*NG + p], g_sinT[m*NG + p]);
    }
    __syncthreads();

    float2 gr[16], gi[16];
    const float2* src = (const float2*)g_G + (size_t)bj * 16 * 2 * 64 + t;
#pragma unroll
    for (int m = 0; m < 16; m++) {
        gr[m] = src[(m*2 + 0)*64];
        gi[m] = src[(m*2 + 1)*64];
    }
    float2 bv = ((const float2*)bias)[t];
    float2* dst = (float2*)out + (size_t)bj * NG * 64 + t;
#pragma unroll
    for (int p = 0; p < 16; p++) {
        float2 E = make_float2(0.f,0.f), O = make_float2(0.f,0.f);
#pragma unroll
        for (int m = 0; m < 16; m++) {
            float2 cs = tcs[m][p];
            if (m & 1) {
                O.x += gr[m].x*cs.x - gi[m].x*cs.y;
                O.y += gr[m].y*cs.x - gi[m].y*cs.y;
            } else {
                E.x += gr[m].x*cs.x - gi[m].x*cs.y;
                E.y += gr[m].y*cs.x - gi[m].y*cs.y;
            }
        }
        dst[p*64]      = make_float2(bv.x + E.x + O.x, bv.y + E.y + O.y);
        dst[(p+16)*64] = make_float2(bv.x + E.x - O.x, bv.y + E.y - O.y);
    }
}

extern "C" void kernel_launch(void* const* d_in, const int* in_sizes, int n_in,
                              void* d_out, int out_size) {
    const float* in   = (const float*)d_in[0];
    const float* w    = (const float*)d_in[1];
    const float* bias = (const float*)d_in[2];
    float* out = (float*)d_out;

    init_tables<<<1, 512>>>();
    kA<<<BATCH*NG, 64>>>(in);
    kB<<<NR, 64>>>();
    kC<<<dim3(32, LMAX), 256>>>(w);
    kD<<<NR, 64>>>();
    kE<<<BATCH*NG, 64>>>(bias, out);
}

// round 15
// speedup vs baseline: 1.4789x; 1.4789x over previous
#include <cuda_runtime.h>
#include <math.h>
#include <stdint.h>

#define BATCH 64
#define NG    32
#define CIN   128
#define COUT  128
#define LMAX  16
#define NR    (BATCH*LMAX*2)   // 2048 rows (b,m,ri)

// ---------------- scratch (device globals; no allocation allowed) ----------
__device__ float g_F[(size_t)BATCH*LMAX*2*NG*CIN];     // [b][m][ri][j][i]
// coef/chat layout: [l][m][ri][b][c]  -> valid region per l = first (l+1)*128 rows
__device__ float g_coef[(size_t)LMAX*2048*CIN];
__device__ float g_chat[(size_t)LMAX*2048*COUT];
__device__ float g_G[(size_t)BATCH*NG*LMAX*2*COUT];    // [b][j][m][ri][o]
__device__ float g_Qw[LMAX*LMAX*NG];                   // [l][m][j] * wj * s_l
__device__ float g_Qs[LMAX*LMAX*NG];                   // [l][m][j] * k_m
__device__ float g_cosT[LMAX*NG];                      // [m][p]
__device__ float g_sinT[LMAX*NG];

// kC smem geometry (floats)
#define APAD 132
#define BPAD 136
#define SM_A_FLOATS (128*APAD)
#define SM_B_FLOATS (128*BPAD)
#define SM_C_BYTES  ((SM_A_FLOATS + SM_B_FLOATS) * 4)   // 137216

__device__ __forceinline__ float to_tf32(float x) {
    float r;
    asm("cvt.rna.tf32.f32 %0, %1;" : "=f"(r) : "f"(x));
    return r;
}

// ---------------- init: Legendre + trig tables, fp32, 512-way parallel -----
__global__ void init_tables() {
    int t = threadIdx.x;                  // 0..511
    int m = t >> 5, j = t & 31;           // one thread per (m, j)
    float sx, cx;
    sincospif((j + 0.5f) / NG, &sx, &cx);
    float wj = sx * ((float)M_PI / NG) * (2.0f * (float)M_PI / NG);

    for (int l = 0; l < m; l++) {
        g_Qw[(l*LMAX + m)*NG + j] = 0.f;
        g_Qs[(l*LMAX + m)*NG + j] = 0.f;
    }

    float Pmm = 1.0f, invf = 1.0f;
    for (int mm = 1; mm <= m; mm++) Pmm = -(2.0f*mm - 1.0f) * sx * Pmm;
    for (int tt = 1; tt <= 2*m; tt++) invf /= (float)tt;
    float rat = invf;
    float pl_2 = 0.0f, pl_1 = 0.0f, pl = 0.0f;
    const float inv4pi = 1.0f / (4.0f * (float)M_PI);
    for (int l = m; l < LMAX; l++) {
        if (l == m)        pl = Pmm;
        else if (l == m+1) pl = (2.0f*m + 1.0f) * cx * Pmm;
        else               pl = ((2.0f*l - 1.0f)*cx*pl_1 - (l + m - 1.0f)*pl_2) / (float)(l - m);
        float Nlm = sqrtf((2.0f*l + 1.0f) * inv4pi * rat);
        float q   = Nlm * pl;
        float sl  = 2.0f*(float)M_PI * sqrtf(4.0f*(float)M_PI / (2.0f*l + 1.0f));
        float km  = (m == 0) ? 1.0f : 2.0f;
        g_Qw[(l*LMAX + m)*NG + j] = q * wj * sl;
        g_Qs[(l*LMAX + m)*NG + j] = q * km;
        pl_2 = pl_1; pl_1 = pl;
        rat *= (float)(l + 1 - m) / (float)(l + 1 + m);
    }

    float sa, ca;
    sincospif(2.0f * (float)m * (float)j / (float)NG, &sa, &ca);
    g_cosT[m*NG + j] = ca;
    g_sinT[m*NG + j] = sa;
}

// ---------------- A: real DFT over phi (half-split), float2 channels -------
__global__ void __launch_bounds__(64) kA(const float* __restrict__ in) {
    int bj = blockIdx.x;                  // b*32 + j (theta)
    int b = bj >> 5, j = bj & 31;
    int t = threadIdx.x;                  // channel pair 0..63
    __shared__ float2 tcs[16][16];        // (cos, sin) packed
    for (int q = t; q < 256; q += 64) {
        int m = q >> 4, p = q & 15;
        tcs[m][p] = make_float2(g_cosT[m*NG + p], g_sinT[m*NG + p]);
    }
    __syncthreads();

    const float2* src = (const float2*)in + (size_t)bj * NG * 64 + t;
    float2 xe[16], xo[16];
#pragma unroll
    for (int p = 0; p < 16; p++) {
        float2 a = src[p*64], c = src[(p+16)*64];
        xe[p] = make_float2(a.x + c.x, a.y + c.y);
        xo[p] = make_float2(a.x - c.x, a.y - c.y);
    }

    float2* Fout = (float2*)g_F;
#pragma unroll
    for (int m = 0; m < 16; m++) {
        float2 fr = make_float2(0.f, 0.f), fi = make_float2(0.f, 0.f);
#pragma unroll
        for (int p = 0; p < 16; p++) {
            float2 cs = tcs[m][p];
            float2 x = (m & 1) ? xo[p] : xe[p];
            fr.x += x.x*cs.x; fr.y += x.y*cs.x;
            fi.x -= x.x*cs.y; fi.y -= x.y*cs.y;
        }
        size_t base = ((((size_t)b*16 + m)*2 + 0)*NG + j)*64 + t;
        Fout[base]          = fr;
        Fout[base + NG*64]  = fi;   // ri=1
    }
}

// ---------------- B: Legendre analysis with reflection symmetry ------------
__global__ void __launch_bounds__(64) kB() {
    int r = blockIdx.x;                   // (b*16+m)*2+ri
    int b = r >> 5, m = (r >> 1) & 15, ri = r & 1;
    int t = threadIdx.x;
    __shared__ float sq[16][16];          // Qw[l][m][j], j<16
    for (int q = t; q < 256; q += 64) {
        int l = q >> 4, j = q & 15;
        sq[l][j] = g_Qw[(l*LMAX + m)*NG + j];
    }
    __syncthreads();

    const float2* src = (const float2*)g_F + (size_t)r * NG * 64 + t;
    float2 fe[16], fo[16];
#pragma unroll
    for (int j = 0; j < 16; j++) {
        float2 a = src[j*64], c = src[(31-j)*64];
        fe[j] = make_float2(a.x + c.x, a.y + c.y);
        fo[j] = make_float2(a.x - c.x, a.y - c.y);
    }

    float2* Cout = (float2*)g_coef;
    size_t rowbase = (size_t)(m*2 + ri)*64 + b;   // within-l row offset
    if ((m & 1) == 0) {
#pragma unroll
        for (int l = 0; l < 16; l++) {
            if (l < m) continue;
            float2 acc = make_float2(0.f, 0.f);
#pragma unroll
            for (int j = 0; j < 16; j++) {
                float q = sq[l][j];
                float2 f = (l & 1) ? fo[j] : fe[j];
                acc.x += q*f.x; acc.y += q*f.y;
            }
            Cout[((size_t)l*2048 + rowbase)*64 + t] = acc;
        }
    } else {
#pragma unroll
        for (int l = 0; l < 16; l++) {
            if (l < m) continue;
            float2 acc = make_float2(0.f, 0.f);
#pragma unroll
            for (int j = 0; j < 16; j++) {
                float q = sq[l][j];
                float2 f = (l & 1) ? fe[j] : fo[j];
                acc.x += q*f.x; acc.y += q*f.y;
            }
            Cout[((size_t)l*2048 + rowbase)*64 + t] = acc;
        }
    }
}

// ---------------- C: per-degree channel mix on tensor cores (tf32 mma) -----
// block tile 128x128x128, 8 warps (4x2), warp tile 32x64; triangular skip
__global__ void __launch_bounds__(256) kC(const float* __restrict__ w) {
    int l = blockIdx.y, mt = blockIdx.x;
    if (mt > l) return;                   // zero region: skip
    extern __shared__ float sm[];
    float* As = sm;                       // [128][APAD]
    float* Bs = sm + SM_A_FLOATS;         // [128][BPAD]

    const float* A = g_coef + ((size_t)l*2048 + (size_t)mt*128)*CIN;
    const float* B = w + l*COUT;          // row k at w[k*2048 + l*128]
    float* C = g_chat + ((size_t)l*2048 + (size_t)mt*128)*COUT;

    int tid = threadIdx.x;

    // load + tf32-convert A (128x128) and B (128x128) into smem
#pragma unroll
    for (int e = 0; e < 16; e++) {
        int lin = tid + e*256;            // float4 index: row = lin>>5, c4 = lin&31
        int row = lin >> 5, c4 = lin & 31;
        float4 va = *(const float4*)&A[row*CIN + c4*4];
        float* d = &As[row*APAD + c4*4];
        d[0] = to_tf32(va.x); d[1] = to_tf32(va.y);
        d[2] = to_tf32(va.z); d[3] = to_tf32(va.w);
        float4 vb = *(const float4*)&B[(size_t)row*(LMAX*COUT) + c4*4];
        float* db = &Bs[row*BPAD + c4*4];
        db[0] = to_tf32(vb.x); db[1] = to_tf32(vb.y);
        db[2] = to_tf32(vb.z); db[3] = to_tf32(vb.w);
    }
    __syncthreads();

    int wid = tid >> 5, lane = tid & 31;
    int g = lane >> 2, tg = lane & 3;     // group / thread-in-group
    int wm = wid & 3, wn = wid >> 2;      // warp row-block (32), col-block (64)
    int rbase = wm*32, cbase = wn*64;

    float acc[2][8][4];
#pragma unroll
    for (int mf = 0; mf < 2; mf++)
#pragma unroll
        for (int nf = 0; nf < 8; nf++)
#pragma unroll
            for (int q = 0; q < 4; q++) acc[mf][nf][q] = 0.f;

    const uint32_t* Au = (const uint32_t*)As;
    const uint32_t* Bu = (const uint32_t*)Bs;

#pragma unroll
    for (int ks = 0; ks < 16; ks++) {
        int k0 = ks*8;
        uint32_t a[2][4];
#pragma unroll
        for (int mf = 0; mf < 2; mf++) {
            int r0 = rbase + mf*16;
            a[mf][0] = Au[(r0 + g    )*APAD + k0 + tg    ];
            a[mf][1] = Au[(r0 + g + 8)*APAD + k0 + tg    ];
            a[mf][2] = Au[(r0 + g    )*APAD + k0 + tg + 4];
            a[mf][3] = Au[(r0 + g + 8)*APAD + k0 + tg + 4];
        }
        uint32_t b[8][2];
#pragma unroll
        for (int nf = 0; nf < 8; nf++) {
            int c0 = cbase + nf*8 + g;
            b[nf][0] = Bu[(k0 + tg    )*BPAD + c0];
            b[nf][1] = Bu[(k0 + tg + 4)*BPAD + c0];
        }
#pragma unroll
        for (int mf = 0; mf < 2; mf++)
#pragma unroll
            for (int nf = 0; nf < 8; nf++) {
                asm volatile(
                    "mma.sync.aligned.m16n8k8.row.col.f32.tf32.tf32.f32 "
                    "{%0,%1,%2,%3}, {%4,%5,%6,%7}, {%8,%9}, {%0,%1,%2,%3};"
                    : "+f"(acc[mf][nf][0]), "+f"(acc[mf][nf][1]),
                      "+f"(acc[mf][nf][2]), "+f"(acc[mf][nf][3])
                    : "r"(a[mf][0]), "r"(a[mf][1]), "r"(a[mf][2]), "r"(a[mf][3]),
                      "r"(b[nf][0]), "r"(b[nf][1]));
            }
    }

    // epilogue: c0,c1 at (g, 2tg, 2tg+1); c2,c3 at (g+8, ...)
#pragma unroll
    for (int mf = 0; mf < 2; mf++) {
        int r0 = rbase + mf*16 + g;
#pragma unroll
        for (int nf = 0; nf < 8; nf++) {
            int c0 = cbase + nf*8 + tg*2;
            *(float2*)&C[(size_t)r0*COUT + c0] =
                make_float2(acc[mf][nf][0], acc[mf][nf][1]);
            *(float2*)&C[(size_t)(r0 + 8)*COUT + c0] =
                make_float2(acc[mf][nf][2], acc[mf][nf][3]);
        }
    }
}

// ---------------- D: Legendre synthesis with reflection symmetry -----------
__global__ void __launch_bounds__(64) kD() {
    int r = blockIdx.x;                   // (b*16+m)*2+ri
    int ri = r & 1, m = (r >> 1) & 15, b = r >> 5;
    int t = threadIdx.x;
    __shared__ float sq[16][16];          // Qs[l][m][j], j<16 (incl. k_m)
    for (int q = t; q < 256; q += 64) {
        int l = q >> 4, j = q & 15;
        sq[l][j] = g_Qs[(l*LMAX + m)*NG + j];
    }
    __syncthreads();

    float2 ch[16];
    const float2* src = (const float2*)g_chat;
    size_t rowbase = (size_t)(m*2 + ri)*64 + b;
#pragma unroll
    for (int l = 0; l < 16; l++)
        ch[l] = (l >= m) ? src[((size_t)l*2048 + rowbase)*64 + t]
                         : make_float2(0.f, 0.f);

    float2* Gout = (float2*)g_G;
    size_t gbase = ((((size_t)b*NG)*16 + m)*2 + ri)*64 + t;
    const size_t jstride = (size_t)16*2*64;

    if ((m & 1) == 0) {
#pragma unroll
        for (int j = 0; j < 16; j++) {
            float2 Ge = make_float2(0.f,0.f), Go = make_float2(0.f,0.f);
#pragma unroll
            for (int l = 0; l < 16; l++) {
                float q = sq[l][j];
                if (l & 1) { Go.x += q*ch[l].x; Go.y += q*ch[l].y; }
                else       { Ge.x += q*ch[l].x; Ge.y += q*ch[l].y; }
            }
            Gout[gbase + (size_t)j*jstride]      = make_float2(Ge.x+Go.x, Ge.y+Go.y);
            Gout[gbase + (size_t)(31-j)*jstride] = make_float2(Ge.x-Go.x, Ge.y-Go.y);
        }
    } else {
#pragma unroll
        for (int j = 0; j < 16; j++) {
            float2 Ge = make_float2(0.f,0.f), Go = make_float2(0.f,0.f);
#pragma unroll
            for (int l = 0; l < 16; l++) {
                float q = sq[l][j];
                if (l & 1) { Ge.x += q*ch[l].x; Ge.y += q*ch[l].y; }
                else       { Go.x += q*ch[l].x; Go.y += q*ch[l].y; }
            }
            Gout[gbase + (size_t)j*jstride]      = make_float2(Ge.x+Go.x, Ge.y+Go.y);
            Gout[gbase + (size_t)(31-j)*jstride] = make_float2(Ge.x-Go.x, Ge.y-Go.y);
        }
    }
}

// ---------------- E: inverse real DFT over phi (half-split) + bias ---------
__global__ void __launch_bounds__(64) kE(const float* __restrict__ bias,
                                         float* __restrict__ out) {
    int bj = blockIdx.x;                  // b*32 + j (theta)
    int t = threadIdx.x;                  // channel pair
    __shared__ float2 tcs[16][16];        // (cos, sin) packed
    for (int q = t; q < 256; q += 64) {
        int m = q >> 4, p = q & 15;
        tcs[m][p] = make_float2(g_cosT[m*NG + p], g_sinT[m*NG + p]);
    }
    __syncthreads();

    float2 gr[16], gi[16];
    const float2* src = (const float2*)g_G + (size_t)bj * 16 * 2 * 64 + t;
#pragma unroll
    for (int m = 0; m < 16; m++) {
        gr[m] = src[(m*2 + 0)*64];
        gi[m] = src[(m*2 + 1)*64];
    }
    float2 bv = ((const float2*)bias)[t];
    float2* dst = (float2*)out + (size_t)bj * NG * 64 + t;
#pragma unroll
    for (int p = 0; p < 16; p++) {
        float2 E = make_float2(0.f,0.f), O = make_float2(0.f,0.f);
#pragma unroll
        for (int m = 0; m < 16; m++) {
            float2 cs = tcs[m][p];
            if (m & 1) {
                O.x += gr[m].x*cs.x - gi[m].x*cs.y;
                O.y += gr[m].y*cs.x - gi[m].y*cs.y;
            } else {
                E.x += gr[m].x*cs.x - gi[m].x*cs.y;
                E.y += gr[m].y*cs.x - gi[m].y*cs.y;
            }
        }
        dst[p*64]      = make_float2(bv.x + E.x + O.x, bv.y + E.y + O.y);
        dst[(p+16)*64] = make_float2(bv.x + E.x - O.x, bv.y + E.y - O.y);
    }
}

extern "C" void kernel_launch(void* const* d_in, const int* in_sizes, int n_in,
                              void* d_out, int out_size) {
    const float* in   = (const float*)d_in[0];
    const float* w    = (const float*)d_in[1];
    const float* bias = (const float*)d_in[2];
    float* out = (float*)d_out;

    cudaFuncSetAttribute(kC, cudaFuncAttributeMaxDynamicSharedMemorySize, SM_C_BYTES);

    init_tables<<<1, 512>>>();
    kA<<<BATCH*NG, 64>>>(in);
    kB<<<NR, 64>>>();
    kC<<<dim3(16, LMAX), 256, SM_C_BYTES>>>(w);
    kD<<<NR, 64>>>();
    kE<<<BATCH*NG, 64>>>(bias, out);
}